// round 1
// baseline (speedup 1.0000x reference)
#include <cuda_runtime.h>
#include <math.h>

// Problem constants (fixed by the dataset: Ns=Nt=8192, D=512)
constexpr int NS_MAX = 8192;
constexpr int BM = 128, BN = 128, BK = 16, TM = 8, TN = 8;
constexpr int NSPLIT = 8;   // deterministic split of the target dimension

// Scratch (device globals — no allocation allowed in kernel_launch)
__device__ float g_sq_s[NS_MAX];
__device__ float g_sq_t[NS_MAX];
__device__ float g_ps[NSPLIT][NS_MAX];
__device__ float g_pc[NSPLIT][NS_MAX];

// ---------------------------------------------------------------------------
// Row sum-of-squares: one warp per row, float4 loads (coalesced).
// ---------------------------------------------------------------------------
__global__ void ccsa_sumsq_kernel(const float* __restrict__ emb,
                                  float* __restrict__ out,
                                  int N, int D4) {
    int warp = (blockIdx.x * blockDim.x + threadIdx.x) >> 5;
    int lane = threadIdx.x & 31;
    if (warp >= N) return;
    const float4* row = reinterpret_cast<const float4*>(emb) + (size_t)warp * D4;
    float s = 0.f;
    for (int i = lane; i < D4; i += 32) {
        float4 v = row[i];
        s += v.x * v.x + v.y * v.y + v.z * v.z + v.w * v.w;
    }
#pragma unroll
    for (int o = 16; o; o >>= 1) s += __shfl_xor_sync(0xffffffffu, s, o);
    if (lane == 0) out[warp] = s;
}

// ---------------------------------------------------------------------------
// Main fused kernel: 128x128 C-tile per block, 8x8 per thread, K tiled by 16.
// Gram element is consumed immediately into per-row loss accumulators.
// Grid: (Ns/BM, NSPLIT). Each block loops over Nt/(BN*NSPLIT) target tiles.
// ---------------------------------------------------------------------------
__global__ __launch_bounds__(256, 2) void ccsa_main_kernel(
    const float* __restrict__ A,   // source_emb [Ns, D]
    const float* __restrict__ B,   // target_emb [Nt, D]
    const int*   __restrict__ ssec,
    const int*   __restrict__ tsec,
    int Nt, int D)
{
    __shared__ __align__(16) float As[BK][BM];
    __shared__ __align__(16) float Bs[BK][BN];
    __shared__ float s_sqs[BM];
    __shared__ float s_sqt[BN];
    __shared__ int   s_ss[BM];
    __shared__ int   s_ts[BN];

    const int tid  = threadIdx.x;
    const int trow = tid >> 4;     // 0..15
    const int tcol = tid & 15;     // 0..15
    const int m0   = blockIdx.x * BM;
    const int split = blockIdx.y;
    const int ntPerSplit = Nt / (BN * NSPLIT);
    const float invD = 1.0f / (float)D;

    if (tid < BM) { s_sqs[tid] = g_sq_s[m0 + tid]; s_ss[tid] = ssec[m0 + tid]; }

    float ls[TM], lc[TM];
#pragma unroll
    for (int i = 0; i < TM; i++) { ls[i] = 0.f; lc[i] = 0.f; }

    for (int nt = 0; nt < ntPerSplit; ++nt) {
        const int n0 = (split * ntPerSplit + nt) * BN;
        if (tid < BN) { s_sqt[tid] = g_sq_t[n0 + tid]; s_ts[tid] = tsec[n0 + tid]; }

        float acc[TM][TN];
#pragma unroll
        for (int i = 0; i < TM; i++)
#pragma unroll
            for (int j = 0; j < TN; j++) acc[i][j] = 0.f;

        for (int k0 = 0; k0 < D; k0 += BK) {
            // Each thread loads 2 float4 of A-tile and 2 of B-tile (transposed store)
#pragma unroll
            for (int q = 0; q < 2; q++) {
                int idx = tid * 2 + q;        // 0..511
                int row = idx >> 2;           // 0..127
                int kc  = (idx & 3) << 2;     // 0,4,8,12
                float4 va = *reinterpret_cast<const float4*>(
                    &A[(size_t)(m0 + row) * D + k0 + kc]);
                As[kc + 0][row] = va.x; As[kc + 1][row] = va.y;
                As[kc + 2][row] = va.z; As[kc + 3][row] = va.w;
                float4 vb = *reinterpret_cast<const float4*>(
                    &B[(size_t)(n0 + row) * D + k0 + kc]);
                Bs[kc + 0][row] = vb.x; Bs[kc + 1][row] = vb.y;
                Bs[kc + 2][row] = vb.z; Bs[kc + 3][row] = vb.w;
            }
            __syncthreads();

#pragma unroll
            for (int k = 0; k < BK; k++) {
                float a[TM], b[TN];
                float4 a0 = *reinterpret_cast<const float4*>(&As[k][trow * TM]);
                float4 a1 = *reinterpret_cast<const float4*>(&As[k][trow * TM + 4]);
                float4 b0 = *reinterpret_cast<const float4*>(&Bs[k][tcol * TN]);
                float4 b1 = *reinterpret_cast<const float4*>(&Bs[k][tcol * TN + 4]);
                a[0] = a0.x; a[1] = a0.y; a[2] = a0.z; a[3] = a0.w;
                a[4] = a1.x; a[5] = a1.y; a[6] = a1.z; a[7] = a1.w;
                b[0] = b0.x; b[1] = b0.y; b[2] = b0.z; b[3] = b0.w;
                b[4] = b1.x; b[5] = b1.y; b[6] = b1.z; b[7] = b1.w;
#pragma unroll
                for (int i = 0; i < TM; i++)
#pragma unroll
                    for (int j = 0; j < TN; j++)
                        acc[i][j] = fmaf(a[i], b[j], acc[i][j]);
            }
            __syncthreads();
        }

        // Epilogue: consume the 8x8 Gram micro-tile into loss accumulators.
#pragma unroll
        for (int i = 0; i < TM; i++) {
            const int   m   = trow * TM + i;
            const float sqs = s_sqs[m];
            const int   sc  = s_ss[m];
            float accs = 0.f, accc = 0.f;
#pragma unroll
            for (int j = 0; j < TN; j++) {
                const int n = tcol * TN + j;
                float d2 = fmaxf(fmaf(-2.f, acc[i][j], sqs + s_sqt[n]), 0.f) * invD;
                if (sc == s_ts[n]) {
                    accs += d2;
                } else if (d2 < 0.25f) {      // hinge nonzero only here (rare)
                    float h = 0.5f - sqrtf(d2);
                    accc += h * h;
                }
            }
            ls[i] += accs; lc[i] += accc;
        }
        __syncthreads();   // protect s_sqt/s_ts before next tile overwrites
    }

    // Block reduction across the 16 column-threads; reuse As as scratch.
    float* red = &As[0][0];  // 2048 floats = BM*16
#pragma unroll
    for (int i = 0; i < TM; i++) red[(trow * TM + i) * 16 + tcol] = ls[i];
    __syncthreads();
    float vs = 0.f;
    if (tid < BM) {
#pragma unroll
        for (int c = 0; c < 16; c++) vs += red[tid * 16 + c];
    }
    __syncthreads();
#pragma unroll
    for (int i = 0; i < TM; i++) red[(trow * TM + i) * 16 + tcol] = lc[i];
    __syncthreads();
    if (tid < BM) {
        float vc = 0.f;
#pragma unroll
        for (int c = 0; c < 16; c++) vc += red[tid * 16 + c];
        g_ps[split][m0 + tid] = vs;
        g_pc[split][m0 + tid] = vc;
    }
}

// ---------------------------------------------------------------------------
// Deterministic final reduction over the NSPLIT partials; applies 1/Nt.
// ---------------------------------------------------------------------------
__global__ void ccsa_reduce_kernel(float* __restrict__ out, int Ns, float invNt) {
    int i = blockIdx.x * blockDim.x + threadIdx.x;
    if (i >= Ns) return;
    float s = 0.f, c = 0.f;
#pragma unroll
    for (int p = 0; p < NSPLIT; p++) { s += g_ps[p][i]; c += g_pc[p][i]; }
    out[i]      = s * invNt;   // loss_s
    out[Ns + i] = c * invNt;   // loss_c
}

// ---------------------------------------------------------------------------
extern "C" void kernel_launch(void* const* d_in, const int* in_sizes, int n_in,
                              void* d_out, int out_size) {
    const float* A  = (const float*)d_in[0];   // source_emb
    const float* B  = (const float*)d_in[1];   // target_emb
    const int*   ss = (const int*)d_in[2];     // source_sec
    const int*   ts = (const int*)d_in[3];     // target_sec

    const int Ns = in_sizes[2];
    const int Nt = in_sizes[3];
    const int D  = in_sizes[0] / Ns;
    float* out = (float*)d_out;

    float* d_sqs = nullptr;
    float* d_sqt = nullptr;
    cudaGetSymbolAddress((void**)&d_sqs, g_sq_s);
    cudaGetSymbolAddress((void**)&d_sqt, g_sq_t);

    // 1) Row sums-of-squares (one warp per row)
    {
        int warps_per_block = 8;
        int blocks_s = (Ns + warps_per_block - 1) / warps_per_block;
        int blocks_t = (Nt + warps_per_block - 1) / warps_per_block;
        ccsa_sumsq_kernel<<<blocks_s, 256>>>(A, d_sqs, Ns, D / 4);
        ccsa_sumsq_kernel<<<blocks_t, 256>>>(B, d_sqt, Nt, D / 4);
    }

    // 2) Fused Gram + loss partials
    {
        dim3 grid(Ns / BM, NSPLIT);
        ccsa_main_kernel<<<grid, 256>>>(A, B, ss, ts, Nt, D);
    }

    // 3) Deterministic reduce + scale
    {
        int blocks = (Ns + 255) / 256;
        ccsa_reduce_kernel<<<blocks, 256>>>(out, Ns, 1.0f / (float)Nt);
    }
}

// round 3
// speedup vs baseline: 7.7943x; 7.7943x over previous
#include <cuda_runtime.h>
#include <cuda_bf16.h>
#include <stdint.h>
#include <math.h>

// ---------------------------------------------------------------------------
// Problem constants (fixed by dataset): Ns = Nt = 8192, D = 512
// ---------------------------------------------------------------------------
constexpr int NS = 8192;
constexpr int NT = 8192;
constexpr int DD = 512;

constexpr int BM = 128;            // CTA tile M (source rows)
constexpr int BN = 128;            // CTA tile N (target rows)
constexpr int BK = 32;             // K per smem stage (bf16) -> 64B rows
constexpr int KITERS = DD / BK;    // 16
constexpr int NTM = NS / BM;       // 64
constexpr int NTN = NT / BN;       // 64

// ---------------------------------------------------------------------------
// Device scratch (no allocation allowed in kernel_launch)
// ---------------------------------------------------------------------------
__device__ __nv_bfloat16 g_Abf[(size_t)NS * DD];
__device__ __nv_bfloat16 g_Bbf[(size_t)NT * DD];
__device__ float g_sq_s[NS];
__device__ float g_sq_t[NT];
__device__ float g_ps[NTN][NS];
__device__ float g_pc[NTN][NS];

// ---------------------------------------------------------------------------
// PTX helpers (portable sm_80+ features only: cp.async, ldmatrix, mma.sync)
// ---------------------------------------------------------------------------
__device__ __forceinline__ uint32_t smem_u32(const void* p) {
    uint32_t a;
    asm("{ .reg .u64 t; cvta.to.shared.u64 t, %1; cvt.u32.u64 %0, t; }"
        : "=r"(a) : "l"(p));
    return a;
}

__device__ __forceinline__ void cpasync16(uint32_t dst, const void* src) {
    asm volatile("cp.async.cg.shared.global [%0], [%1], 16;"
                 :: "r"(dst), "l"(src) : "memory");
}
__device__ __forceinline__ void cpasync_commit() {
    asm volatile("cp.async.commit_group;" ::: "memory");
}
template <int N>
__device__ __forceinline__ void cpasync_wait() {
    asm volatile("cp.async.wait_group %0;" :: "n"(N) : "memory");
}

__device__ __forceinline__ void ldsm_x4(uint32_t& r0, uint32_t& r1,
                                        uint32_t& r2, uint32_t& r3,
                                        uint32_t addr) {
    asm volatile("ldmatrix.sync.aligned.m8n8.x4.shared.b16 {%0,%1,%2,%3}, [%4];"
                 : "=r"(r0), "=r"(r1), "=r"(r2), "=r"(r3) : "r"(addr));
}

__device__ __forceinline__ void mma_bf16(float& d0, float& d1, float& d2, float& d3,
                                         uint32_t a0, uint32_t a1, uint32_t a2, uint32_t a3,
                                         uint32_t b0, uint32_t b1) {
    asm volatile(
        "mma.sync.aligned.m16n8k16.row.col.f32.bf16.bf16.f32 "
        "{%0,%1,%2,%3}, {%4,%5,%6,%7}, {%8,%9}, {%0,%1,%2,%3};"
        : "+f"(d0), "+f"(d1), "+f"(d2), "+f"(d3)
        : "r"(a0), "r"(a1), "r"(a2), "r"(a3), "r"(b0), "r"(b1));
}

// ---------------------------------------------------------------------------
// Prep: fp32 -> bf16 (rn) + row sum-of-squares. 1 warp / row.
// ---------------------------------------------------------------------------
__global__ void ccsa_prep_kernel(const float* __restrict__ emb,
                                 __nv_bfloat16* __restrict__ out_bf,
                                 float* __restrict__ out_sq, int N) {
    int row  = (blockIdx.x * blockDim.x + threadIdx.x) >> 5;
    int lane = threadIdx.x & 31;
    if (row >= N) return;
    const float4* src = reinterpret_cast<const float4*>(emb) + (size_t)row * (DD / 4);
    uint2* dst = reinterpret_cast<uint2*>(out_bf) + (size_t)row * (DD / 4);
    float s = 0.f;
#pragma unroll
    for (int i = lane; i < DD / 4; i += 32) {
        float4 v = src[i];
        s += v.x * v.x + v.y * v.y + v.z * v.z + v.w * v.w;
        __nv_bfloat162 h0 = __float22bfloat162_rn(make_float2(v.x, v.y));
        __nv_bfloat162 h1 = __float22bfloat162_rn(make_float2(v.z, v.w));
        uint2 o;
        o.x = *reinterpret_cast<uint32_t*>(&h0);
        o.y = *reinterpret_cast<uint32_t*>(&h1);
        dst[i] = o;
    }
#pragma unroll
    for (int o = 16; o; o >>= 1) s += __shfl_xor_sync(0xffffffffu, s, o);
    if (lane == 0) out_sq[row] = s;
}

// ---------------------------------------------------------------------------
// Main: bf16 mma.sync GEMM tile (128x128) + fused loss epilogue.
// 8 warps in 2x4 grid, warp tile 64x32. cp.async double-buffered smem.
// Smem 16B-chunk swizzle: chunk' = chunk ^ ((row>>1) & 3)  (64B rows)
//  -> conflict-free for both cp.async stores and ldmatrix loads.
// ---------------------------------------------------------------------------
__global__ __launch_bounds__(256, 2) void ccsa_mma_kernel(
    const __nv_bfloat16* __restrict__ Abf,
    const __nv_bfloat16* __restrict__ Bbf,
    const float* __restrict__ sq_s,
    const float* __restrict__ sq_t,
    const int* __restrict__ ssec,
    const int* __restrict__ tsec) {
    __shared__ __align__(128) uint8_t smA[2][BM * 64];
    __shared__ __align__(128) uint8_t smB[2][BN * 64];
    __shared__ float s_sqs[BM], s_sqt[BN];
    __shared__ int   s_ss[BM],  s_ts[BN];
    __shared__ float redS[4][BM], redC[4][BM];

    const int tid  = threadIdx.x;
    const int wid  = tid >> 5;
    const int lane = tid & 31;
    const int wm   = wid >> 2;     // 0..1
    const int wn   = wid & 3;      // 0..3
    const int nt   = blockIdx.x;   // N tile
    const int mt   = blockIdx.y;   // M tile
    const int m0   = mt * BM;
    const int n0   = nt * BN;

    const uint32_t smA0 = smem_u32(&smA[0][0]);
    const uint32_t smB0 = smem_u32(&smB[0][0]);

    // side data into smem
    if (tid < BM) { s_sqs[tid] = sq_s[m0 + tid]; s_ss[tid] = ssec[m0 + tid]; }
    else if (tid < BM + BN) {
        int i = tid - BM;
        s_sqt[i] = sq_t[n0 + i]; s_ts[i] = tsec[n0 + i];
    }

    // ldmatrix lane geometry (identical structure for A and B)
    const int ltile = lane >> 3;                 // 0..3
    const int lrow8 = lane & 7;                  // 0..7
    const int khalf = ltile >> 1;                // 0/1: k 0..7 vs 8..15 of a k16 step
    const int roff  = (ltile & 1) * 8 + lrow8;   // 0..15 row offset inside 16-row frag
    const int xr    = (roff >> 1) & 3;           // swizzle term (mf/p-invariant)

    uint32_t aAddr[4];                            // per m-frag base (buffer 0)
#pragma unroll
    for (int mf = 0; mf < 4; ++mf)
        aAddr[mf] = smA0 + (uint32_t)(wm * 64 + mf * 16 + roff) * 64;
    uint32_t bAddr[2];                            // per n-frag-pair base (buffer 0)
#pragma unroll
    for (int p = 0; p < 2; ++p)
        bAddr[p] = smB0 + (uint32_t)(wn * 32 + p * 16 + roff) * 64;

    // global tile bases
    const char* Ag = reinterpret_cast<const char*>(Abf + (size_t)m0 * DD);
    const char* Bg = reinterpret_cast<const char*>(Bbf + (size_t)n0 * DD);

    float acc[4][4][4];
#pragma unroll
    for (int i = 0; i < 4; ++i)
#pragma unroll
        for (int j = 0; j < 4; ++j)
#pragma unroll
            for (int e = 0; e < 4; ++e) acc[i][j][e] = 0.f;

    // tile loader: stage kt into buffer kt&1
    auto load_tile = [&](int kt) {
        const int buf = kt & 1;
        const uint32_t da = smA0 + buf * (BM * 64);
        const uint32_t db = smB0 + buf * (BN * 64);
#pragma unroll
        for (int i = 0; i < 2; ++i) {       // A: 512 16B-chunks / 256 thr
            int idx = i * 256 + tid;
            int r = idx >> 2, c = idx & 3;
            cpasync16(da + (uint32_t)(r * 64 + ((c ^ ((r >> 1) & 3)) << 4)),
                      Ag + ((size_t)r * DD + kt * BK + c * 8) * 2);
        }
#pragma unroll
        for (int i = 0; i < 2; ++i) {       // B
            int idx = i * 256 + tid;
            int r = idx >> 2, c = idx & 3;
            cpasync16(db + (uint32_t)(r * 64 + ((c ^ ((r >> 1) & 3)) << 4)),
                      Bg + ((size_t)r * DD + kt * BK + c * 8) * 2);
        }
        cpasync_commit();
    };

    load_tile(0);

    for (int kt = 0; kt < KITERS; ++kt) {
        if (kt + 1 < KITERS) {
            load_tile(kt + 1);
            cpasync_wait<1>();
        } else {
            cpasync_wait<0>();
        }
        __syncthreads();

        const uint32_t bufOff = (uint32_t)((kt & 1) ? BM * 64 : 0);
        const uint32_t bufOffB = (uint32_t)((kt & 1) ? BN * 64 : 0);
#pragma unroll
        for (int s = 0; s < 2; ++s) {        // two k16 steps per BK=32 stage
            const uint32_t coff = (uint32_t)(((s * 2 + khalf) ^ xr) << 4);
            uint32_t a[4][4];
#pragma unroll
            for (int mf = 0; mf < 4; ++mf)
                ldsm_x4(a[mf][0], a[mf][1], a[mf][2], a[mf][3],
                        aAddr[mf] + bufOff + coff);
            uint32_t b[2][4];
#pragma unroll
            for (int p = 0; p < 2; ++p)
                ldsm_x4(b[p][0], b[p][1], b[p][2], b[p][3],
                        bAddr[p] + bufOffB + coff);
            // nfrag nf: pair p = nf>>1, sub = nf&1: b_lo = b[p][sub], b_hi = b[p][sub+2]
#pragma unroll
            for (int mf = 0; mf < 4; ++mf)
#pragma unroll
                for (int nf = 0; nf < 4; ++nf)
                    mma_bf16(acc[mf][nf][0], acc[mf][nf][1],
                             acc[mf][nf][2], acc[mf][nf][3],
                             a[mf][0], a[mf][1], a[mf][2], a[mf][3],
                             b[nf >> 1][nf & 1], b[nf >> 1][(nf & 1) + 2]);
        }
        __syncthreads();
    }

    // ---- fused epilogue ----
    const int g   = lane >> 2;    // accum row group 0..7
    const int tig = lane & 3;     // accum col group
    const float invD = 1.0f / (float)DD;

#pragma unroll
    for (int mf = 0; mf < 4; ++mf) {
        const int rlo = wm * 64 + mf * 16 + g;
        const int rhi = rlo + 8;
        const float sqlo = s_sqs[rlo], sqhi = s_sqs[rhi];
        const int   sclo = s_ss[rlo],  schi = s_ss[rhi];
        float lsl = 0.f, lcl = 0.f, lsh = 0.f, lch = 0.f;
#pragma unroll
        for (int nf = 0; nf < 4; ++nf) {
#pragma unroll
            for (int e = 0; e < 2; ++e) {
                const int n = wn * 32 + nf * 8 + tig * 2 + e;
                const float sqt = s_sqt[n];
                const int   tc  = s_ts[n];
                float d2l = fmaxf(fmaf(-2.f, acc[mf][nf][e],     sqlo + sqt), 0.f) * invD;
                float d2h = fmaxf(fmaf(-2.f, acc[mf][nf][2 + e], sqhi + sqt), 0.f) * invD;
                if (sclo == tc) lsl += d2l;
                else if (d2l < 0.25f) { float h = 0.5f - sqrtf(d2l); lcl += h * h; }
                if (schi == tc) lsh += d2h;
                else if (d2h < 0.25f) { float h = 0.5f - sqrtf(d2h); lch += h * h; }
            }
        }
        // quad reduce across tig lanes (bits 0,1 of lane id)
#pragma unroll
        for (int o = 1; o <= 2; o <<= 1) {
            lsl += __shfl_xor_sync(0xffffffffu, lsl, o);
            lcl += __shfl_xor_sync(0xffffffffu, lcl, o);
            lsh += __shfl_xor_sync(0xffffffffu, lsh, o);
            lch += __shfl_xor_sync(0xffffffffu, lch, o);
        }
        if (tig == 0) {
            redS[wn][rlo] = lsl; redC[wn][rlo] = lcl;
            redS[wn][rhi] = lsh; redC[wn][rhi] = lch;
        }
    }
    __syncthreads();

    if (tid < BM) {
        float s = redS[0][tid] + redS[1][tid] + redS[2][tid] + redS[3][tid];
        float c = redC[0][tid] + redC[1][tid] + redC[2][tid] + redC[3][tid];
        g_ps[nt][m0 + tid] = s;
        g_pc[nt][m0 + tid] = c;
    }
}

// ---------------------------------------------------------------------------
// Deterministic final reduce over the NTN column-tile partials; applies 1/Nt.
// ---------------------------------------------------------------------------
__global__ void ccsa_reduce_kernel(float* __restrict__ out, float invNt) {
    int i = blockIdx.x * blockDim.x + threadIdx.x;
    if (i >= NS) return;
    float s = 0.f, c = 0.f;
#pragma unroll
    for (int p = 0; p < NTN; ++p) {
        s += g_ps[p][i];
        c += g_pc[p][i];
    }
    out[i]      = s * invNt;
    out[NS + i] = c * invNt;
}

// ---------------------------------------------------------------------------
extern "C" void kernel_launch(void* const* d_in, const int* in_sizes, int n_in,
                              void* d_out, int out_size) {
    const float* A  = (const float*)d_in[0];
    const float* B  = (const float*)d_in[1];
    const int*   ss = (const int*)d_in[2];
    const int*   ts = (const int*)d_in[3];
    float* out = (float*)d_out;

    __nv_bfloat16 *d_Abf = nullptr, *d_Bbf = nullptr;
    float *d_sqs = nullptr, *d_sqt = nullptr;
    cudaGetSymbolAddress((void**)&d_Abf, g_Abf);
    cudaGetSymbolAddress((void**)&d_Bbf, g_Bbf);
    cudaGetSymbolAddress((void**)&d_sqs, g_sq_s);
    cudaGetSymbolAddress((void**)&d_sqt, g_sq_t);

    // 1) convert + sumsq (8 warps / block)
    ccsa_prep_kernel<<<NS / 8, 256>>>(A, d_Abf, d_sqs, NS);
    ccsa_prep_kernel<<<NT / 8, 256>>>(B, d_Bbf, d_sqt, NT);

    // 2) fused mma.sync GEMM + loss partials
    dim3 grid(NTN, NTM);
    ccsa_mma_kernel<<<grid, 256>>>(d_Abf, d_Bbf, d_sqs, d_sqt, ss, ts);

    // 3) deterministic reduce
    ccsa_reduce_kernel<<<(NS + 255) / 256, 256>>>(out, 1.0f / (float)NT);
}